// round 3
// baseline (speedup 1.0000x reference)
#include <cuda_runtime.h>

// ---------------- SSIM constants ----------------
#define IMG_H 512
#define IMG_W 512
#define RAD   5          // (11-1)/2
#define KS    11

#define TW 32            // output tile width
#define TH 16            // output tile height
#define IW (TW + 2*RAD)  // 42 input tile width
#define IH (TH + 2*RAD)  // 26 input tile height
#define IWP 44           // padded smem stride for input planes
#define HWP 33           // padded smem stride for horizontal-blur planes
#define NTHREADS 256

// Gaussian 1D weights: g[i] = exp(-i^2 / (2*1.5^2)), normalized.
// (normalized outer product == outer product of normalized 1D, exactly)
#define G0d 1.0
#define G1d 0.8007374029168081   /* exp(-1/4.5)  */
#define G2d 0.4111122905071874   /* exp(-4/4.5)  */
#define G3d 0.1353352832366127   /* exp(-9/4.5)  */
#define G4d 0.0285655007845504   /* exp(-16/4.5) */
#define G5d 0.0038659201394728   /* exp(-25/4.5) */
#define GSd (G0d + 2.0*(G1d+G2d+G3d+G4d+G5d))

__device__ constexpr float WK[11] = {
    (float)(G5d/GSd), (float)(G4d/GSd), (float)(G3d/GSd), (float)(G2d/GSd), (float)(G1d/GSd),
    (float)(G0d/GSd),
    (float)(G1d/GSd), (float)(G2d/GSd), (float)(G3d/GSd), (float)(G4d/GSd), (float)(G5d/GSd)
};

#define C1F 0.0001f      // 0.01^2
#define C2F 0.0009f      // 0.03^2

__device__ double g_ssim_sum;

__global__ void zero_acc_kernel() { g_ssim_sum = 0.0; }

__global__ void finalize_kernel(float* out, double invN) {
    out[0] = (float)(1.0 - g_ssim_sum * invN);
}

__global__ __launch_bounds__(NTHREADS) void ssim_tile_kernel(
    const float* __restrict__ pred,
    const float* __restrict__ target)
{
    // 5 fields: p, t, p*p, t*t, p*t
    __shared__ float sP[5][IH][IWP];   // input planes with halo
    __shared__ float sH[5][IH][HWP];   // after horizontal blur
    __shared__ float red[NTHREADS / 32];

    const int tx0 = blockIdx.x * TW;
    const int ty0 = blockIdx.y * TH;
    const size_t img_off = (size_t)blockIdx.z * (IMG_H * IMG_W);
    const float* __restrict__ p = pred + img_off;
    const float* __restrict__ t = target + img_off;

    // ---- Phase A: load halo tile, compute pointwise products ----
    for (int idx = threadIdx.x; idx < IH * IW; idx += NTHREADS) {
        int r = idx / IW, c = idx - r * IW;
        int gy = ty0 + r - RAD;
        int gx = tx0 + c - RAD;
        float pv = 0.0f, tv = 0.0f;
        if (gy >= 0 && gy < IMG_H && gx >= 0 && gx < IMG_W) {
            int g = gy * IMG_W + gx;
            pv = p[g];
            tv = t[g];
        }
        sP[0][r][c] = pv;
        sP[1][r][c] = tv;
        sP[2][r][c] = pv * pv;
        sP[3][r][c] = tv * tv;
        sP[4][r][c] = pv * tv;
    }
    __syncthreads();

    // ---- Phase B: horizontal blur (IH rows x TW cols, 5 fields) ----
    for (int idx = threadIdx.x; idx < IH * TW; idx += NTHREADS) {
        int r = idx / TW, c = idx - r * TW;
        float a0 = 0.f, a1 = 0.f, a2 = 0.f, a3 = 0.f, a4 = 0.f;
        #pragma unroll
        for (int k = 0; k < KS; k++) {
            float w = WK[k];
            a0 = fmaf(sP[0][r][c + k], w, a0);
            a1 = fmaf(sP[1][r][c + k], w, a1);
            a2 = fmaf(sP[2][r][c + k], w, a2);
            a3 = fmaf(sP[3][r][c + k], w, a3);
            a4 = fmaf(sP[4][r][c + k], w, a4);
        }
        sH[0][r][c] = a0;
        sH[1][r][c] = a1;
        sH[2][r][c] = a2;
        sH[3][r][c] = a3;
        sH[4][r][c] = a4;
    }
    __syncthreads();

    // ---- Phase C: vertical blur + SSIM map + local sum ----
    float acc = 0.0f;
    for (int idx = threadIdx.x; idx < TH * TW; idx += NTHREADS) {
        int r = idx / TW, c = idx - r * TW;
        float m0 = 0.f, m1 = 0.f, m2 = 0.f, m3 = 0.f, m4 = 0.f;
        #pragma unroll
        for (int k = 0; k < KS; k++) {
            float w = WK[k];
            m0 = fmaf(sH[0][r + k][c], w, m0);
            m1 = fmaf(sH[1][r + k][c], w, m1);
            m2 = fmaf(sH[2][r + k][c], w, m2);
            m3 = fmaf(sH[3][r + k][c], w, m3);
            m4 = fmaf(sH[4][r + k][c], w, m4);
        }
        float mu_p = m0, mu_t = m1;
        float mu_p2 = mu_p * mu_p;
        float mu_t2 = mu_t * mu_t;
        float mu_pt = mu_p * mu_t;
        float sig_p = m2 - mu_p2;
        float sig_t = m3 - mu_t2;
        float sig_pt = m4 - mu_pt;
        float num = (2.0f * mu_pt + C1F) * (2.0f * sig_pt + C2F);
        float den = (mu_p2 + mu_t2 + C1F) * (sig_p + sig_t + C2F);
        acc += __fdividef(num, den);   // ssim value; loss handled in finalize
    }

    // ---- Phase D: block reduction -> one double atomicAdd ----
    #pragma unroll
    for (int o = 16; o > 0; o >>= 1)
        acc += __shfl_down_sync(0xFFFFFFFFu, acc, o);
    if ((threadIdx.x & 31) == 0)
        red[threadIdx.x >> 5] = acc;
    __syncthreads();
    if (threadIdx.x < NTHREADS / 32) {
        float v = red[threadIdx.x];
        #pragma unroll
        for (int o = (NTHREADS / 64); o > 0; o >>= 1)
            v += __shfl_down_sync(0xFFFFFFFFu, v, o);
        if (threadIdx.x == 0)
            atomicAdd(&g_ssim_sum, (double)v);
    }
}

extern "C" void kernel_launch(void* const* d_in, const int* in_sizes, int n_in,
                              void* d_out, int out_size)
{
    const float* pred   = (const float*)d_in[0];
    const float* target = (const float*)d_in[1];
    float* out = (float*)d_out;

    const long long n = in_sizes[0];                 // 32*3*512*512
    const int imgs = (int)(n / (IMG_H * IMG_W));     // 96 planes

    zero_acc_kernel<<<1, 1>>>();

    dim3 grid(IMG_W / TW, IMG_H / TH, imgs);
    ssim_tile_kernel<<<grid, NTHREADS>>>(pred, target);

    finalize_kernel<<<1, 1>>>(out, 1.0 / (double)n);
}

// round 4
// speedup vs baseline: 2.3153x; 2.3153x over previous
#include <cuda_runtime.h>

#define IMG_H 512
#define IMG_W 512
#define RAD   5
#define KS    11

#define W_T 32           // tile width  (output cols)
#define H_T 64           // tile height (output rows)
#define NC  (W_T + 2*RAD)   // 42 halo columns
#define SSTRIDE 43          // padded smem row stride
#define NTHREADS 256
#define VTASKS (NC * (H_T / 8))   // 42 * 8 = 336 vertical tasks

// Gaussian 1D weights, exactly normalized (outer product of normalized 1D
// equals the normalized 2D kernel).
#define G0d 1.0
#define G1d 0.8007374029168081   /* exp(-1/4.5)  */
#define G2d 0.4111122905071874   /* exp(-4/4.5)  */
#define G3d 0.1353352832366127   /* exp(-9/4.5)  */
#define G4d 0.0285655007845504   /* exp(-16/4.5) */
#define G5d 0.0038659201394728   /* exp(-25/4.5) */
#define GSd (G0d + 2.0*(G1d+G2d+G3d+G4d+G5d))

__device__ constexpr float WK[11] = {
    (float)(G5d/GSd), (float)(G4d/GSd), (float)(G3d/GSd), (float)(G2d/GSd), (float)(G1d/GSd),
    (float)(G0d/GSd),
    (float)(G1d/GSd), (float)(G2d/GSd), (float)(G3d/GSd), (float)(G4d/GSd), (float)(G5d/GSd)
};

#define C1F 0.0001f
#define C2F 0.0009f

#define SMEM_BYTES (5 * H_T * SSTRIDE * 4)   // 55040

__device__ double g_ssim_sum;

__global__ void zero_acc_kernel() { g_ssim_sum = 0.0; }

__global__ void finalize_kernel(float* out, double invN) {
    out[0] = (float)(1.0 - g_ssim_sum * invN);
}

__global__ __launch_bounds__(NTHREADS) void ssim_tile_kernel(
    const float* __restrict__ pred,
    const float* __restrict__ target)
{
    extern __shared__ float sV[];            // [5][H_T][SSTRIDE]
    __shared__ float red[NTHREADS / 32];

    const int tx0 = blockIdx.x * W_T;
    const int ty0 = blockIdx.y * H_T;
    const size_t img_off = (size_t)blockIdx.z * (IMG_H * IMG_W);
    const float* __restrict__ p = pred + img_off;
    const float* __restrict__ t = target + img_off;

    // ---- Phase V: vertical blur straight from gmem, scatter into registers ----
    // Task = (halo column c in [0,42), 8-row chunk). Each task reads 18 input
    // rows of p,t, forms the 5 fields inline, scatter-accumulates 8 outputs/field.
    for (int task = threadIdx.x; task < VTASKS; task += NTHREADS) {
        const int c     = task % NC;         // 0..41
        const int chunk = task / NC;         // 0..7
        const int gx    = tx0 + c - RAD;
        const bool xok  = ((unsigned)gx < (unsigned)IMG_W);
        const int gy0   = ty0 + chunk * 8 - RAD;

        float acc[5][8];
        #pragma unroll
        for (int f = 0; f < 5; f++)
            #pragma unroll
            for (int o = 0; o < 8; o++)
                acc[f][o] = 0.0f;

        #pragma unroll
        for (int i = 0; i < 18; i++) {
            const int gy = gy0 + i;
            float pv = 0.0f, tv = 0.0f;
            if (xok && (unsigned)gy < (unsigned)IMG_H) {
                const int g = gy * IMG_W + gx;
                pv = p[g];
                tv = t[g];
            }
            const float f0 = pv, f1 = tv;
            const float f2 = pv * pv, f3 = tv * tv, f4 = pv * tv;
            #pragma unroll
            for (int o = 0; o < 8; o++) {
                const int k = i - o;
                if (k >= 0 && k < KS) {           // compile-time pruned
                    const float w = WK[k];
                    acc[0][o] = fmaf(f0, w, acc[0][o]);
                    acc[1][o] = fmaf(f1, w, acc[1][o]);
                    acc[2][o] = fmaf(f2, w, acc[2][o]);
                    acc[3][o] = fmaf(f3, w, acc[3][o]);
                    acc[4][o] = fmaf(f4, w, acc[4][o]);
                }
            }
        }

        #pragma unroll
        for (int o = 0; o < 8; o++) {
            const int r = chunk * 8 + o;
            #pragma unroll
            for (int f = 0; f < 5; f++)
                sV[(f * H_T + r) * SSTRIDE + c] = acc[f][o];
        }
    }
    __syncthreads();

    // ---- Phase H: horizontal blur from smem + SSIM, one task per thread ----
    // Task = (row r in [0,64), 8-col chunk q in [0,4)).
    float ssum = 0.0f;
    {
        const int r = threadIdx.x >> 2;
        const int q = threadIdx.x & 3;
        const int cbase = q * 8;

        float m[5][8];
        #pragma unroll
        for (int f = 0; f < 5; f++)
            #pragma unroll
            for (int o = 0; o < 8; o++)
                m[f][o] = 0.0f;

        #pragma unroll
        for (int i = 0; i < 18; i++) {
            const int ci = cbase + i;        // 0..41
            const float v0 = sV[(0 * H_T + r) * SSTRIDE + ci];
            const float v1 = sV[(1 * H_T + r) * SSTRIDE + ci];
            const float v2 = sV[(2 * H_T + r) * SSTRIDE + ci];
            const float v3 = sV[(3 * H_T + r) * SSTRIDE + ci];
            const float v4 = sV[(4 * H_T + r) * SSTRIDE + ci];
            #pragma unroll
            for (int o = 0; o < 8; o++) {
                const int k = i - o;
                if (k >= 0 && k < KS) {
                    const float w = WK[k];
                    m[0][o] = fmaf(v0, w, m[0][o]);
                    m[1][o] = fmaf(v1, w, m[1][o]);
                    m[2][o] = fmaf(v2, w, m[2][o]);
                    m[3][o] = fmaf(v3, w, m[3][o]);
                    m[4][o] = fmaf(v4, w, m[4][o]);
                }
            }
        }

        #pragma unroll
        for (int o = 0; o < 8; o++) {
            const float mu_p = m[0][o], mu_t = m[1][o];
            const float mu_p2 = mu_p * mu_p;
            const float mu_t2 = mu_t * mu_t;
            const float mu_pt = mu_p * mu_t;
            const float sig_p  = m[2][o] - mu_p2;
            const float sig_t  = m[3][o] - mu_t2;
            const float sig_pt = m[4][o] - mu_pt;
            const float num = (2.0f * mu_pt + C1F) * (2.0f * sig_pt + C2F);
            const float den = (mu_p2 + mu_t2 + C1F) * (sig_p + sig_t + C2F);
            ssum += __fdividef(num, den);
        }
    }

    // ---- block reduction -> one double atomicAdd ----
    #pragma unroll
    for (int o = 16; o > 0; o >>= 1)
        ssum += __shfl_down_sync(0xFFFFFFFFu, ssum, o);
    if ((threadIdx.x & 31) == 0)
        red[threadIdx.x >> 5] = ssum;
    __syncthreads();
    if (threadIdx.x < NTHREADS / 32) {
        float v = red[threadIdx.x];
        #pragma unroll
        for (int o = (NTHREADS / 64); o > 0; o >>= 1)
            v += __shfl_down_sync(0xFFFFFFFFu, v, o);
        if (threadIdx.x == 0)
            atomicAdd(&g_ssim_sum, (double)v);
    }
}

extern "C" void kernel_launch(void* const* d_in, const int* in_sizes, int n_in,
                              void* d_out, int out_size)
{
    const float* pred   = (const float*)d_in[0];
    const float* target = (const float*)d_in[1];
    float* out = (float*)d_out;

    const long long n = in_sizes[0];                 // 32*3*512*512
    const int imgs = (int)(n / (IMG_H * IMG_W));     // 96 planes

    cudaFuncSetAttribute(ssim_tile_kernel,
                         cudaFuncAttributeMaxDynamicSharedMemorySize, SMEM_BYTES);

    zero_acc_kernel<<<1, 1>>>();

    dim3 grid(IMG_W / W_T, IMG_H / H_T, imgs);
    ssim_tile_kernel<<<grid, NTHREADS, SMEM_BYTES>>>(pred, target);

    finalize_kernel<<<1, 1>>>(out, 1.0 / (double)n);
}

// round 5
// speedup vs baseline: 2.9446x; 1.2718x over previous
#include <cuda_runtime.h>

#define IMG_H 512
#define IMG_W 512
#define RAD   5
#define KS    11

#define W_T 32
#define H_T 64
#define NC  (W_T + 2*RAD)   // 42 halo columns
#define SSTRIDE 43          // padded smem row stride
#define NTHREADS 256
#define VTASKS (NC * (H_T / 8))   // 336

#define G0d 1.0
#define G1d 0.8007374029168081
#define G2d 0.4111122905071874
#define G3d 0.1353352832366127
#define G4d 0.0285655007845504
#define G5d 0.0038659201394728
#define GSd (G0d + 2.0*(G1d+G2d+G3d+G4d+G5d))

__device__ constexpr float WK[11] = {
    (float)(G5d/GSd), (float)(G4d/GSd), (float)(G3d/GSd), (float)(G2d/GSd), (float)(G1d/GSd),
    (float)(G0d/GSd),
    (float)(G1d/GSd), (float)(G2d/GSd), (float)(G3d/GSd), (float)(G4d/GSd), (float)(G5d/GSd)
};

#define C1F 0.0001f
#define C2F 0.0009f

#define SMEM_BYTES (5 * H_T * SSTRIDE * 4)   // 55040

__device__ double g_ssim_sum;

__global__ void zero_acc_kernel() { g_ssim_sum = 0.0; }

__global__ void finalize_kernel(float* out, double invN) {
    out[0] = (float)(1.0 - g_ssim_sum * invN);
}

// Vertical blur of the 5 fields straight from gmem into smem.
// INTERIOR=true blocks skip all bounds logic: one base pointer per task,
// all 36 loads become immediate-offset LDGs.
template<bool INTERIOR>
__device__ __forceinline__ void v_phase(
    const float* __restrict__ p, const float* __restrict__ t,
    float* __restrict__ sV, int tx0, int ty0)
{
    for (int task = threadIdx.x; task < VTASKS; task += NTHREADS) {
        const int c     = task % NC;         // 0..41
        const int chunk = task / NC;         // 0..7
        const int gx    = tx0 + c - RAD;
        const int gy0   = ty0 + chunk * 8 - RAD;

        float acc[5][8];
        #pragma unroll
        for (int f = 0; f < 5; f++)
            #pragma unroll
            for (int o = 0; o < 8; o++)
                acc[f][o] = 0.0f;

        const float* pp = p + (long)gy0 * IMG_W + gx;
        const float* tt = t + (long)gy0 * IMG_W + gx;
        const bool xok = ((unsigned)gx < (unsigned)IMG_W);

        #pragma unroll
        for (int i = 0; i < 18; i++) {
            float pv, tv;
            if (INTERIOR) {
                pv = pp[i * IMG_W];
                tv = tt[i * IMG_W];
            } else {
                const int gy = gy0 + i;
                const bool ok = xok && ((unsigned)gy < (unsigned)IMG_H);
                pv = ok ? pp[i * IMG_W] : 0.0f;
                tv = ok ? tt[i * IMG_W] : 0.0f;
            }
            const float f2 = pv * pv, f3 = tv * tv, f4 = pv * tv;
            #pragma unroll
            for (int o = 0; o < 8; o++) {
                const int k = i - o;
                if (k >= 0 && k < KS) {          // compile-time pruned
                    const float w = WK[k];
                    acc[0][o] = fmaf(pv, w, acc[0][o]);
                    acc[1][o] = fmaf(tv, w, acc[1][o]);
                    acc[2][o] = fmaf(f2, w, acc[2][o]);
                    acc[3][o] = fmaf(f3, w, acc[3][o]);
                    acc[4][o] = fmaf(f4, w, acc[4][o]);
                }
            }
        }

        #pragma unroll
        for (int o = 0; o < 8; o++) {
            const int r = chunk * 8 + o;
            #pragma unroll
            for (int f = 0; f < 5; f++)
                sV[(f * H_T + r) * SSTRIDE + c] = acc[f][o];
        }
    }
}

__global__ __launch_bounds__(NTHREADS, 2) void ssim_tile_kernel(
    const float* __restrict__ pred,
    const float* __restrict__ target)
{
    extern __shared__ float sV[];            // [5][H_T][SSTRIDE]
    __shared__ float red[NTHREADS / 32];

    const int tx0 = blockIdx.x * W_T;
    const int ty0 = blockIdx.y * H_T;
    const size_t img_off = (size_t)blockIdx.z * (IMG_H * IMG_W);
    const float* __restrict__ p = pred + img_off;
    const float* __restrict__ t = target + img_off;

    // ---- Phase V ----
    const bool interior =
        (blockIdx.x > 0) && (blockIdx.x < gridDim.x - 1) &&
        (blockIdx.y > 0) && (blockIdx.y < gridDim.y - 1);
    if (interior) v_phase<true >(p, t, sV, tx0, ty0);
    else          v_phase<false>(p, t, sV, tx0, ty0);
    __syncthreads();

    // ---- Phase H: horizontal blur from smem + SSIM ----
    float ssum = 0.0f;
    {
        const int r = threadIdx.x >> 2;
        const int q = threadIdx.x & 3;
        const int cbase = q * 8;

        float m[5][8];
        #pragma unroll
        for (int f = 0; f < 5; f++)
            #pragma unroll
            for (int o = 0; o < 8; o++)
                m[f][o] = 0.0f;

        #pragma unroll
        for (int i = 0; i < 18; i++) {
            const int ci = cbase + i;
            const float v0 = sV[(0 * H_T + r) * SSTRIDE + ci];
            const float v1 = sV[(1 * H_T + r) * SSTRIDE + ci];
            const float v2 = sV[(2 * H_T + r) * SSTRIDE + ci];
            const float v3 = sV[(3 * H_T + r) * SSTRIDE + ci];
            const float v4 = sV[(4 * H_T + r) * SSTRIDE + ci];
            #pragma unroll
            for (int o = 0; o < 8; o++) {
                const int k = i - o;
                if (k >= 0 && k < KS) {
                    const float w = WK[k];
                    m[0][o] = fmaf(v0, w, m[0][o]);
                    m[1][o] = fmaf(v1, w, m[1][o]);
                    m[2][o] = fmaf(v2, w, m[2][o]);
                    m[3][o] = fmaf(v3, w, m[3][o]);
                    m[4][o] = fmaf(v4, w, m[4][o]);
                }
            }
        }

        #pragma unroll
        for (int o = 0; o < 8; o++) {
            const float mu_p = m[0][o], mu_t = m[1][o];
            const float mu_p2 = mu_p * mu_p;
            const float mu_t2 = mu_t * mu_t;
            const float mu_pt = mu_p * mu_t;
            const float sig_p  = m[2][o] - mu_p2;
            const float sig_t  = m[3][o] - mu_t2;
            const float sig_pt = m[4][o] - mu_pt;
            const float num = (2.0f * mu_pt + C1F) * (2.0f * sig_pt + C2F);
            const float den = (mu_p2 + mu_t2 + C1F) * (sig_p + sig_t + C2F);
            ssum += __fdividef(num, den);
        }
    }

    // ---- block reduction -> one double atomicAdd ----
    #pragma unroll
    for (int o = 16; o > 0; o >>= 1)
        ssum += __shfl_down_sync(0xFFFFFFFFu, ssum, o);
    if ((threadIdx.x & 31) == 0)
        red[threadIdx.x >> 5] = ssum;
    __syncthreads();
    if (threadIdx.x < NTHREADS / 32) {
        float v = red[threadIdx.x];
        #pragma unroll
        for (int o = (NTHREADS / 64); o > 0; o >>= 1)
            v += __shfl_down_sync(0xFFFFFFFFu, v, o);
        if (threadIdx.x == 0)
            atomicAdd(&g_ssim_sum, (double)v);
    }
}

extern "C" void kernel_launch(void* const* d_in, const int* in_sizes, int n_in,
                              void* d_out, int out_size)
{
    const float* pred   = (const float*)d_in[0];
    const float* target = (const float*)d_in[1];
    float* out = (float*)d_out;

    const long long n = in_sizes[0];                 // 32*3*512*512
    const int imgs = (int)(n / (IMG_H * IMG_W));     // 96 planes

    cudaFuncSetAttribute(ssim_tile_kernel,
                         cudaFuncAttributeMaxDynamicSharedMemorySize, SMEM_BYTES);

    zero_acc_kernel<<<1, 1>>>();

    dim3 grid(IMG_W / W_T, IMG_H / H_T, imgs);
    ssim_tile_kernel<<<grid, NTHREADS, SMEM_BYTES>>>(pred, target);

    finalize_kernel<<<1, 1>>>(out, 1.0 / (double)n);
}

// round 6
// speedup vs baseline: 3.2818x; 1.1145x over previous
#include <cuda_runtime.h>

#define IMG_H 512
#define IMG_W 512
#define RAD   5
#define KS    11

#define H_T 16                 // output rows per block (full 512-col width)
#define SSTRIDE 522            // 512 + 2*RAD halo cols; 522 % 4 == 2 -> LDS.64 conflict-free
#define NTHREADS 512

#define G0d 1.0
#define G1d 0.8007374029168081
#define G2d 0.4111122905071874
#define G3d 0.1353352832366127
#define G4d 0.0285655007845504
#define G5d 0.0038659201394728
#define GSd (G0d + 2.0*(G1d+G2d+G3d+G4d+G5d))

__device__ constexpr float WK[11] = {
    (float)(G5d/GSd), (float)(G4d/GSd), (float)(G3d/GSd), (float)(G2d/GSd), (float)(G1d/GSd),
    (float)(G0d/GSd),
    (float)(G1d/GSd), (float)(G2d/GSd), (float)(G3d/GSd), (float)(G4d/GSd), (float)(G5d/GSd)
};

#define C1F 0.0001f
#define C2F 0.0009f

#define SMEM_BYTES (5 * H_T * SSTRIDE * 4)   // 167,040

__device__ double g_ssim_sum;

__global__ void zero_acc_kernel() { g_ssim_sum = 0.0; }

__global__ void finalize_kernel(float* out, double invN) {
    out[0] = (float)(1.0 - g_ssim_sum * invN);
}

// Vertical blur of 5 fields for one column, 8 output rows, straight from gmem.
// smem col j represents image col j-RAD; V writes j = col+RAD.
template<bool INTERIOR>
__device__ __forceinline__ void v_phase(
    const float* __restrict__ p, const float* __restrict__ t,
    float* __restrict__ sV, int ty0)
{
    #pragma unroll
    for (int wave = 0; wave < 2; wave++) {
        const int task  = threadIdx.x + wave * NTHREADS;
        const int col   = task & 511;            // 0..511 (coalesced per warp)
        const int chunk = task >> 9;             // 0..1
        const int gy0   = ty0 + chunk * 8 - RAD;

        float acc[5][8];
        #pragma unroll
        for (int f = 0; f < 5; f++)
            #pragma unroll
            for (int o = 0; o < 8; o++)
                acc[f][o] = 0.0f;

        const float* pp = p + (long)gy0 * IMG_W + col;
        const float* tt = t + (long)gy0 * IMG_W + col;

        #pragma unroll
        for (int i = 0; i < 18; i++) {
            float pv, tv;
            if (INTERIOR) {
                pv = pp[i * IMG_W];
                tv = tt[i * IMG_W];
            } else {
                const bool ok = ((unsigned)(gy0 + i) < (unsigned)IMG_H);
                pv = ok ? pp[i * IMG_W] : 0.0f;
                tv = ok ? tt[i * IMG_W] : 0.0f;
            }
            const float f2 = pv * pv, f3 = tv * tv, f4 = pv * tv;
            #pragma unroll
            for (int o = 0; o < 8; o++) {
                const int k = i - o;
                if (k >= 0 && k < KS) {          // compile-time pruned
                    const float w = WK[k];
                    acc[0][o] = fmaf(pv, w, acc[0][o]);
                    acc[1][o] = fmaf(tv, w, acc[1][o]);
                    acc[2][o] = fmaf(f2, w, acc[2][o]);
                    acc[3][o] = fmaf(f3, w, acc[3][o]);
                    acc[4][o] = fmaf(f4, w, acc[4][o]);
                }
            }
        }

        #pragma unroll
        for (int o = 0; o < 8; o++) {
            const int r = chunk * 8 + o;
            #pragma unroll
            for (int f = 0; f < 5; f++)
                sV[(f * H_T + r) * SSTRIDE + col + RAD] = acc[f][o];
        }
    }
}

__global__ __launch_bounds__(NTHREADS, 1) void ssim_tile_kernel(
    const float* __restrict__ pred,
    const float* __restrict__ target)
{
    extern __shared__ float sV[];            // [5][H_T][SSTRIDE]
    __shared__ float red[NTHREADS / 32];

    const int ty0 = blockIdx.x * H_T;
    const size_t img_off = (size_t)blockIdx.y * (IMG_H * IMG_W);
    const float* __restrict__ p = pred + img_off;
    const float* __restrict__ t = target + img_off;

    // ---- zero the 10 halo columns (left 5 + right 5) for all fields/rows ----
    // 5 fields * 16 rows * 10 cols = 800 entries
    if (threadIdx.x < 800) {
        const int z = threadIdx.x;
        const int cz = z % 10;
        const int rz = (z / 10) % H_T;
        const int fz = z / (10 * H_T);
        const int j = (cz < 5) ? cz : (SSTRIDE - 10 + cz);
        sV[(fz * H_T + rz) * SSTRIDE + j] = 0.0f;
    }

    // ---- Phase V ----
    const bool interior = (blockIdx.x > 0) && (blockIdx.x < gridDim.x - 1);
    if (interior) v_phase<true >(p, t, sV, ty0);
    else          v_phase<false>(p, t, sV, ty0);
    __syncthreads();

    // ---- Phase H: horizontal blur from smem (float2 loads) + SSIM ----
    float ssum = 0.0f;
    #pragma unroll
    for (int wave = 0; wave < 2; wave++) {
        const int task  = threadIdx.x + wave * NTHREADS;
        const int r     = task & (H_T - 1);
        const int chunk = task >> 4;             // 0..63
        const int c0    = chunk * 8;             // output col base; smem j base = c0 (even)

        const float2* row0 = (const float2*)&sV[(0 * H_T + r) * SSTRIDE + c0];
        const float2* row1 = (const float2*)&sV[(1 * H_T + r) * SSTRIDE + c0];
        const float2* row2 = (const float2*)&sV[(2 * H_T + r) * SSTRIDE + c0];
        const float2* row3 = (const float2*)&sV[(3 * H_T + r) * SSTRIDE + c0];
        const float2* row4 = (const float2*)&sV[(4 * H_T + r) * SSTRIDE + c0];

        float m[5][8];
        #pragma unroll
        for (int f = 0; f < 5; f++)
            #pragma unroll
            for (int o = 0; o < 8; o++)
                m[f][o] = 0.0f;

        #pragma unroll
        for (int i2 = 0; i2 < 9; i2++) {
            const float2 v0 = row0[i2];
            const float2 v1 = row1[i2];
            const float2 v2 = row2[i2];
            const float2 v3 = row3[i2];
            const float2 v4 = row4[i2];
            #pragma unroll
            for (int half = 0; half < 2; half++) {
                const int i = 2 * i2 + half;
                const float a0 = half ? v0.y : v0.x;
                const float a1 = half ? v1.y : v1.x;
                const float a2 = half ? v2.y : v2.x;
                const float a3 = half ? v3.y : v3.x;
                const float a4 = half ? v4.y : v4.x;
                #pragma unroll
                for (int o = 0; o < 8; o++) {
                    const int k = i - o;
                    if (k >= 0 && k < KS) {      // compile-time pruned
                        const float w = WK[k];
                        m[0][o] = fmaf(a0, w, m[0][o]);
                        m[1][o] = fmaf(a1, w, m[1][o]);
                        m[2][o] = fmaf(a2, w, m[2][o]);
                        m[3][o] = fmaf(a3, w, m[3][o]);
                        m[4][o] = fmaf(a4, w, m[4][o]);
                    }
                }
            }
        }

        #pragma unroll
        for (int o = 0; o < 8; o++) {
            const float mu_p = m[0][o], mu_t = m[1][o];
            const float mu_p2 = mu_p * mu_p;
            const float mu_t2 = mu_t * mu_t;
            const float mu_pt = mu_p * mu_t;
            const float sig_p  = m[2][o] - mu_p2;
            const float sig_t  = m[3][o] - mu_t2;
            const float sig_pt = m[4][o] - mu_pt;
            const float num = (2.0f * mu_pt + C1F) * (2.0f * sig_pt + C2F);
            const float den = (mu_p2 + mu_t2 + C1F) * (sig_p + sig_t + C2F);
            ssum += __fdividef(num, den);
        }
    }

    // ---- block reduction -> one double atomicAdd ----
    #pragma unroll
    for (int o = 16; o > 0; o >>= 1)
        ssum += __shfl_down_sync(0xFFFFFFFFu, ssum, o);
    if ((threadIdx.x & 31) == 0)
        red[threadIdx.x >> 5] = ssum;
    __syncthreads();
    if (threadIdx.x < NTHREADS / 32) {
        float v = red[threadIdx.x];
        #pragma unroll
        for (int o = (NTHREADS / 64); o > 0; o >>= 1)
            v += __shfl_down_sync(0xFFFFFFFFu, v, o);
        if (threadIdx.x == 0)
            atomicAdd(&g_ssim_sum, (double)v);
    }
}

extern "C" void kernel_launch(void* const* d_in, const int* in_sizes, int n_in,
                              void* d_out, int out_size)
{
    const float* pred   = (const float*)d_in[0];
    const float* target = (const float*)d_in[1];
    float* out = (float*)d_out;

    const long long n = in_sizes[0];                 // 32*3*512*512
    const int imgs = (int)(n / (IMG_H * IMG_W));     // 96 planes

    cudaFuncSetAttribute(ssim_tile_kernel,
                         cudaFuncAttributeMaxDynamicSharedMemorySize, SMEM_BYTES);

    zero_acc_kernel<<<1, 1>>>();

    dim3 grid(IMG_H / H_T, imgs);                    // (32, 96)
    ssim_tile_kernel<<<grid, NTHREADS, SMEM_BYTES>>>(pred, target);

    finalize_kernel<<<1, 1>>>(out, 1.0 / (double)n);
}

// round 8
// speedup vs baseline: 3.6523x; 1.1129x over previous
#include <cuda_runtime.h>

#define IMG_H 512
#define IMG_W 512
#define RAD   5
#define KS    11

#define H_T 8                  // output rows per block (full 512-col width)
#define SSTRIDE 522            // 512 + 10 halo; /2 = 261 odd -> LDS.64 bank math works
#define NTHREADS 512

#define G0d 1.0
#define G1d 0.8007374029168081
#define G2d 0.4111122905071874
#define G3d 0.1353352832366127
#define G4d 0.0285655007845504
#define G5d 0.0038659201394728
#define GSd (G0d + 2.0*(G1d+G2d+G3d+G4d+G5d))

__device__ constexpr float WK[11] = {
    (float)(G5d/GSd), (float)(G4d/GSd), (float)(G3d/GSd), (float)(G2d/GSd), (float)(G1d/GSd),
    (float)(G0d/GSd),
    (float)(G1d/GSd), (float)(G2d/GSd), (float)(G3d/GSd), (float)(G4d/GSd), (float)(G5d/GSd)
};

#define C1F 0.0001f
#define C2F 0.0009f

#define SMEM_BYTES (5 * H_T * SSTRIDE * 4)   // 83,520 -> 2 blocks/SM

__device__ double g_ssim_sum;

__global__ void zero_acc_kernel() { g_ssim_sum = 0.0; }

__global__ void finalize_kernel(float* out, double invN) {
    out[0] = (float)(1.0 - g_ssim_sum * invN);
}

// Vertical blur of 5 fields for one column (= threadIdx.x), 8 output rows,
// straight from gmem into smem. One task per thread, no tail.
template<bool INTERIOR>
__device__ __forceinline__ void v_phase(
    const float* __restrict__ p, const float* __restrict__ t,
    float* __restrict__ sV, int ty0)
{
    const int col = threadIdx.x;             // 0..511, coalesced
    const int gy0 = ty0 - RAD;

    float acc[5][8];
    #pragma unroll
    for (int f = 0; f < 5; f++)
        #pragma unroll
        for (int o = 0; o < 8; o++)
            acc[f][o] = 0.0f;

    const float* pp = p + (long)gy0 * IMG_W + col;
    const float* tt = t + (long)gy0 * IMG_W + col;

    #pragma unroll
    for (int i = 0; i < 18; i++) {
        float pv, tv;
        if (INTERIOR) {
            pv = pp[i * IMG_W];
            tv = tt[i * IMG_W];
        } else {
            const bool ok = ((unsigned)(gy0 + i) < (unsigned)IMG_H);
            pv = ok ? pp[i * IMG_W] : 0.0f;
            tv = ok ? tt[i * IMG_W] : 0.0f;
        }
        const float f2 = pv * pv, f3 = tv * tv, f4 = pv * tv;
        #pragma unroll
        for (int o = 0; o < 8; o++) {
            const int k = i - o;
            if (k >= 0 && k < KS) {          // compile-time pruned
                const float w = WK[k];
                acc[0][o] = fmaf(pv, w, acc[0][o]);
                acc[1][o] = fmaf(tv, w, acc[1][o]);
                acc[2][o] = fmaf(f2, w, acc[2][o]);
                acc[3][o] = fmaf(f3, w, acc[3][o]);
                acc[4][o] = fmaf(f4, w, acc[4][o]);
            }
        }
    }

    #pragma unroll
    for (int o = 0; o < 8; o++)
        #pragma unroll
        for (int f = 0; f < 5; f++)
            sV[(f * H_T + o) * SSTRIDE + col + RAD] = acc[f][o];
}

__global__ __launch_bounds__(NTHREADS, 2) void ssim_tile_kernel(
    const float* __restrict__ pred,
    const float* __restrict__ target)
{
    extern __shared__ float sV[];            // [5][H_T][SSTRIDE]
    __shared__ float red[NTHREADS / 32];

    const int ty0 = blockIdx.x * H_T;
    const size_t img_off = (size_t)blockIdx.y * (IMG_H * IMG_W);
    const float* __restrict__ p = pred + img_off;
    const float* __restrict__ t = target + img_off;

    // ---- zero the 10 halo columns: 5 fields * 8 rows * 10 cols = 400 ----
    if (threadIdx.x < 400) {
        const int z = threadIdx.x;
        const int cz = z % 10;
        const int rz = (z / 10) % H_T;
        const int fz = z / (10 * H_T);
        const int j = (cz < 5) ? cz : (SSTRIDE - 10 + cz);
        sV[(fz * H_T + rz) * SSTRIDE + j] = 0.0f;
    }

    // ---- Phase V ----
    const bool interior = (blockIdx.x > 0) && (blockIdx.x < gridDim.x - 1);
    if (interior) v_phase<true >(p, t, sV, ty0);
    else          v_phase<false>(p, t, sV, ty0);
    __syncthreads();

    // ---- Phase H: one task per thread. Chunk mapping makes half-warp chunk
    // pairs 2 apart (float2 bank offset 8) -> conflict-free LDS.64 with the
    // odd 261-float2 row stride.
    float ssum = 0.0f;
    {
        const int tid = threadIdx.x;
        const int r  = tid & 7;
        const int b3 = (tid >> 3) & 1;       // chunkLocal within half-warp
        const int b4 = (tid >> 4) & 1;       // half-warp select
        const int chunk = (tid >> 5) * 4 + 2 * b3 + b4;   // 0..63, bijective
        const int c0 = chunk * 8;            // even -> float2 aligned

        const float2* row0 = (const float2*)&sV[(0 * H_T + r) * SSTRIDE + c0];
        const float2* row1 = (const float2*)&sV[(1 * H_T + r) * SSTRIDE + c0];
        const float2* row2 = (const float2*)&sV[(2 * H_T + r) * SSTRIDE + c0];
        const float2* row3 = (const float2*)&sV[(3 * H_T + r) * SSTRIDE + c0];
        const float2* row4 = (const float2*)&sV[(4 * H_T + r) * SSTRIDE + c0];

        float m[5][8];
        #pragma unroll
        for (int f = 0; f < 5; f++)
            #pragma unroll
            for (int o = 0; o < 8; o++)
                m[f][o] = 0.0f;

        #pragma unroll
        for (int i2 = 0; i2 < 9; i2++) {
            const float2 v0 = row0[i2];
            const float2 v1 = row1[i2];
            const float2 v2 = row2[i2];
            const float2 v3 = row3[i2];
            const float2 v4 = row4[i2];
            #pragma unroll
            for (int half = 0; half < 2; half++) {
                const int i = 2 * i2 + half;
                const float a0 = half ? v0.y : v0.x;
                const float a1 = half ? v1.y : v1.x;
                const float a2 = half ? v2.y : v2.x;
                const float a3 = half ? v3.y : v3.x;
                const float a4 = half ? v4.y : v4.x;
                #pragma unroll
                for (int o = 0; o < 8; o++) {
                    const int k = i - o;
                    if (k >= 0 && k < KS) {  // compile-time pruned
                        const float w = WK[k];
                        m[0][o] = fmaf(a0, w, m[0][o]);
                        m[1][o] = fmaf(a1, w, m[1][o]);
                        m[2][o] = fmaf(a2, w, m[2][o]);
                        m[3][o] = fmaf(a3, w, m[3][o]);
                        m[4][o] = fmaf(a4, w, m[4][o]);
                    }
                }
            }
        }

        #pragma unroll
        for (int o = 0; o < 8; o++) {
            const float mu_p = m[0][o], mu_t = m[1][o];
            const float mu_p2 = mu_p * mu_p;
            const float mu_t2 = mu_t * mu_t;
            const float mu_pt = mu_p * mu_t;
            const float sig_p  = m[2][o] - mu_p2;
            const float sig_t  = m[3][o] - mu_t2;
            const float sig_pt = m[4][o] - mu_pt;
            const float num = (2.0f * mu_pt + C1F) * (2.0f * sig_pt + C2F);
            const float den = (mu_p2 + mu_t2 + C1F) * (sig_p + sig_t + C2F);
            ssum += __fdividef(num, den);
        }
    }

    // ---- block reduction -> one double atomicAdd ----
    #pragma unroll
    for (int o = 16; o > 0; o >>= 1)
        ssum += __shfl_down_sync(0xFFFFFFFFu, ssum, o);
    if ((threadIdx.x & 31) == 0)
        red[threadIdx.x >> 5] = ssum;
    __syncthreads();
    if (threadIdx.x < NTHREADS / 32) {
        float v = red[threadIdx.x];
        #pragma unroll
        for (int o = (NTHREADS / 64); o > 0; o >>= 1)
            v += __shfl_down_sync(0xFFFFFFFFu, v, o);
        if (threadIdx.x == 0)
            atomicAdd(&g_ssim_sum, (double)v);
    }
}

extern "C" void kernel_launch(void* const* d_in, const int* in_sizes, int n_in,
                              void* d_out, int out_size)
{
    const float* pred   = (const float*)d_in[0];
    const float* target = (const float*)d_in[1];
    float* out = (float*)d_out;

    const long long n = in_sizes[0];                 // 32*3*512*512
    const int imgs = (int)(n / (IMG_H * IMG_W));     // 96 planes

    cudaFuncSetAttribute(ssim_tile_kernel,
                         cudaFuncAttributeMaxDynamicSharedMemorySize, SMEM_BYTES);

    zero_acc_kernel<<<1, 1>>>();

    dim3 grid(IMG_H / H_T, imgs);                    // (64, 96)
    ssim_tile_kernel<<<grid, NTHREADS, SMEM_BYTES>>>(pred, target);

    finalize_kernel<<<1, 1>>>(out, 1.0 / (double)n);
}

// round 9
// speedup vs baseline: 3.6921x; 1.0109x over previous
#include <cuda_runtime.h>

#define IMG_H 512
#define IMG_W 512
#define RAD   5
#define KS    11

#define H_T 8
#define SSTRIDE 522
#define NTHREADS 512

#define G0d 1.0
#define G1d 0.8007374029168081
#define G2d 0.4111122905071874
#define G3d 0.1353352832366127
#define G4d 0.0285655007845504
#define G5d 0.0038659201394728
#define GSd (G0d + 2.0*(G1d+G2d+G3d+G4d+G5d))

__device__ constexpr float WK[11] = {
    (float)(G5d/GSd), (float)(G4d/GSd), (float)(G3d/GSd), (float)(G2d/GSd), (float)(G1d/GSd),
    (float)(G0d/GSd),
    (float)(G1d/GSd), (float)(G2d/GSd), (float)(G3d/GSd), (float)(G4d/GSd), (float)(G5d/GSd)
};

#define C1F 0.0001f
#define C2F 0.0009f

#define SMEM_BYTES (5 * H_T * SSTRIDE * 4)   // 83,520 -> 2 blocks/SM

typedef unsigned long long u64;

__device__ __forceinline__ u64 pack2(float x, float y) {
    u64 r; asm("mov.b64 %0, {%1, %2};" : "=l"(r) : "f"(x), "f"(y)); return r;
}
__device__ __forceinline__ void unpack2(u64 v, float& x, float& y) {
    asm("mov.b64 {%0, %1}, %2;" : "=f"(x), "=f"(y) : "l"(v));
}
__device__ __forceinline__ void fma2(u64& d, u64 a, u64 b) {
    asm("fma.rn.f32x2 %0, %1, %2, %0;" : "+l"(d) : "l"(a), "l"(b));
}
__device__ __forceinline__ u64 mul2(u64 a, u64 b) {
    u64 r; asm("mul.rn.f32x2 %0, %1, %2;" : "=l"(r) : "l"(a), "l"(b)); return r;
}

__device__ double g_ssim_sum;   // zero-initialized at load; finalize restores 0

__global__ void finalize_kernel(float* out, double invN) {
    out[0] = (float)(1.0 - g_ssim_sum * invN);
    g_ssim_sum = 0.0;           // restore invariant for next replay
}

// Vertical blur: one column per thread, 8 output rows, packed fields.
template<bool INTERIOR>
__device__ __forceinline__ void v_phase(
    const float* __restrict__ p, const float* __restrict__ t,
    float* __restrict__ sV, int ty0)
{
    const int col = threadIdx.x;
    const int gy0 = ty0 - RAD;

    u64   acc01[8], acc23[8];
    float acc4[8];
    #pragma unroll
    for (int o = 0; o < 8; o++) { acc01[o] = 0ull; acc23[o] = 0ull; acc4[o] = 0.0f; }

    const float* pp = p + (long)gy0 * IMG_W + col;
    const float* tt = t + (long)gy0 * IMG_W + col;

    #pragma unroll
    for (int i = 0; i < 18; i++) {
        float pv, tv;
        if (INTERIOR) {
            pv = pp[i * IMG_W];
            tv = tt[i * IMG_W];
        } else {
            const bool ok = ((unsigned)(gy0 + i) < (unsigned)IMG_H);
            pv = ok ? pp[i * IMG_W] : 0.0f;
            tv = ok ? tt[i * IMG_W] : 0.0f;
        }
        const u64   a01 = pack2(pv, tv);
        const u64   a23 = mul2(a01, a01);       // (p*p, t*t)
        const float a4  = pv * tv;
        #pragma unroll
        for (int o = 0; o < 8; o++) {
            const int k = i - o;
            if (k >= 0 && k < KS) {              // compile-time pruned
                const int kk = (k < 6) ? k : (10 - k);   // symmetric weights
                const u64 ww = pack2(WK[kk], WK[kk]);    // 64-bit constant
                fma2(acc01[o], a01, ww);
                fma2(acc23[o], a23, ww);
                acc4[o] = fmaf(a4, WK[kk], acc4[o]);
            }
        }
    }

    float* base = sV + col + RAD;
    #pragma unroll
    for (int o = 0; o < 8; o++) {
        float x0, x1, x2, x3;
        unpack2(acc01[o], x0, x1);
        unpack2(acc23[o], x2, x3);
        base[(0 * H_T + o) * SSTRIDE] = x0;
        base[(1 * H_T + o) * SSTRIDE] = x1;
        base[(2 * H_T + o) * SSTRIDE] = x2;
        base[(3 * H_T + o) * SSTRIDE] = x3;
        base[(4 * H_T + o) * SSTRIDE] = acc4[o];
    }
}

__global__ __launch_bounds__(NTHREADS, 2) void ssim_tile_kernel(
    const float* __restrict__ pred,
    const float* __restrict__ target)
{
    extern __shared__ float sV[];            // [5][H_T][SSTRIDE]
    __shared__ float red[NTHREADS / 32];

    const int ty0 = blockIdx.x * H_T;
    const size_t img_off = (size_t)blockIdx.y * (IMG_H * IMG_W);
    const float* __restrict__ p = pred + img_off;
    const float* __restrict__ t = target + img_off;

    // ---- zero the 10 halo columns: 5 fields * 8 rows * 10 cols = 400 ----
    if (threadIdx.x < 400) {
        const int z = threadIdx.x;
        const int cz = z % 10;
        const int rz = (z / 10) % H_T;
        const int fz = z / (10 * H_T);
        const int j = (cz < 5) ? cz : (SSTRIDE - 10 + cz);
        sV[(fz * H_T + rz) * SSTRIDE + j] = 0.0f;
    }

    // ---- Phase V ----
    const bool interior = (blockIdx.x > 0) && (blockIdx.x < gridDim.x - 1);
    if (interior) v_phase<true >(p, t, sV, ty0);
    else          v_phase<false>(p, t, sV, ty0);
    __syncthreads();

    // ---- Phase H: packed horizontal blur + SSIM ----
    float ssum = 0.0f;
    {
        const int tid = threadIdx.x;
        const int r  = tid & 7;
        const int b3 = (tid >> 3) & 1;
        const int b4 = (tid >> 4) & 1;
        const int chunk = (tid >> 5) * 4 + 2 * b3 + b4;   // conflict-free remap
        const int c0 = chunk * 8;

        const float* hb = sV + r * SSTRIDE + c0;   // base; field offsets are immediates

        u64   m01[8], m23[8];
        float m4[8];
        #pragma unroll
        for (int o = 0; o < 8; o++) { m01[o] = 0ull; m23[o] = 0ull; m4[o] = 0.0f; }

        #pragma unroll
        for (int i2 = 0; i2 < 9; i2++) {
            const float2 v0 = *(const float2*)(hb + 0 * H_T * SSTRIDE + 2 * i2);
            const float2 v1 = *(const float2*)(hb + 1 * H_T * SSTRIDE + 2 * i2);
            const float2 v2 = *(const float2*)(hb + 2 * H_T * SSTRIDE + 2 * i2);
            const float2 v3 = *(const float2*)(hb + 3 * H_T * SSTRIDE + 2 * i2);
            const float2 v4 = *(const float2*)(hb + 4 * H_T * SSTRIDE + 2 * i2);
            #pragma unroll
            for (int half = 0; half < 2; half++) {
                const int i = 2 * i2 + half;
                const float a0 = half ? v0.y : v0.x;
                const float a1 = half ? v1.y : v1.x;
                const float a2 = half ? v2.y : v2.x;
                const float a3 = half ? v3.y : v3.x;
                const float a4 = half ? v4.y : v4.x;
                const u64 a01 = pack2(a0, a1);
                const u64 a23 = pack2(a2, a3);
                #pragma unroll
                for (int o = 0; o < 8; o++) {
                    const int k = i - o;
                    if (k >= 0 && k < KS) {
                        const int kk = (k < 6) ? k : (10 - k);
                        const u64 ww = pack2(WK[kk], WK[kk]);
                        fma2(m01[o], a01, ww);
                        fma2(m23[o], a23, ww);
                        m4[o] = fmaf(a4, WK[kk], m4[o]);
                    }
                }
            }
        }

        #pragma unroll
        for (int o = 0; o < 8; o++) {
            float mu_p, mu_t, bp2, bt2;
            unpack2(m01[o], mu_p, mu_t);
            unpack2(m23[o], bp2, bt2);
            const float mu_p2 = mu_p * mu_p;
            const float mu_t2 = mu_t * mu_t;
            const float mu_pt = mu_p * mu_t;
            const float sig_p  = bp2 - mu_p2;
            const float sig_t  = bt2 - mu_t2;
            const float sig_pt = m4[o] - mu_pt;
            const float num = (2.0f * mu_pt + C1F) * (2.0f * sig_pt + C2F);
            const float den = (mu_p2 + mu_t2 + C1F) * (sig_p + sig_t + C2F);
            ssum += __fdividef(num, den);
        }
    }

    // ---- block reduction -> one double atomicAdd ----
    #pragma unroll
    for (int o = 16; o > 0; o >>= 1)
        ssum += __shfl_down_sync(0xFFFFFFFFu, ssum, o);
    if ((threadIdx.x & 31) == 0)
        red[threadIdx.x >> 5] = ssum;
    __syncthreads();
    if (threadIdx.x < NTHREADS / 32) {
        float v = red[threadIdx.x];
        #pragma unroll
        for (int o = (NTHREADS / 64); o > 0; o >>= 1)
            v += __shfl_down_sync(0xFFFFFFFFu, v, o);
        if (threadIdx.x == 0)
            atomicAdd(&g_ssim_sum, (double)v);
    }
}

extern "C" void kernel_launch(void* const* d_in, const int* in_sizes, int n_in,
                              void* d_out, int out_size)
{
    const float* pred   = (const float*)d_in[0];
    const float* target = (const float*)d_in[1];
    float* out = (float*)d_out;

    const long long n = in_sizes[0];                 // 32*3*512*512
    const int imgs = (int)(n / (IMG_H * IMG_W));     // 96 planes

    cudaFuncSetAttribute(ssim_tile_kernel,
                         cudaFuncAttributeMaxDynamicSharedMemorySize, SMEM_BYTES);

    dim3 grid(IMG_H / H_T, imgs);                    // (64, 96)
    ssim_tile_kernel<<<grid, NTHREADS, SMEM_BYTES>>>(pred, target);

    finalize_kernel<<<1, 1>>>(out, 1.0 / (double)n);
}

// round 10
// speedup vs baseline: 3.7253x; 1.0090x over previous
#include <cuda_runtime.h>

#define IMG_H 512
#define IMG_W 512
#define RAD   5
#define KS    11

#define H_T 8
#define SSTRIDE 522
#define NTHREADS 512

#define G0d 1.0
#define G1d 0.8007374029168081
#define G2d 0.4111122905071874
#define G3d 0.1353352832366127
#define G4d 0.0285655007845504
#define G5d 0.0038659201394728
#define GSd (G0d + 2.0*(G1d+G2d+G3d+G4d+G5d))

__device__ constexpr float WK[11] = {
    (float)(G5d/GSd), (float)(G4d/GSd), (float)(G3d/GSd), (float)(G2d/GSd), (float)(G1d/GSd),
    (float)(G0d/GSd),
    (float)(G1d/GSd), (float)(G2d/GSd), (float)(G3d/GSd), (float)(G4d/GSd), (float)(G5d/GSd)
};

#define C1F 0.0001f
#define C2F 0.0009f

#define SMEM_BYTES (5 * H_T * SSTRIDE * 4)   // 83,520 -> 2 blocks/SM

typedef unsigned long long u64;

__device__ __forceinline__ u64 pack2(float x, float y) {
    u64 r; asm("mov.b64 %0, {%1, %2};" : "=l"(r) : "f"(x), "f"(y)); return r;
}
__device__ __forceinline__ void unpack2(u64 v, float& x, float& y) {
    asm("mov.b64 {%0, %1}, %2;" : "=f"(x), "=f"(y) : "l"(v));
}
__device__ __forceinline__ void fma2(u64& d, u64 a, u64 b) {
    asm("fma.rn.f32x2 %0, %1, %2, %0;" : "+l"(d) : "l"(a), "l"(b));
}
__device__ __forceinline__ u64 mul2(u64 a, u64 b) {
    u64 r; asm("mul.rn.f32x2 %0, %1, %2;" : "=l"(r) : "l"(a), "l"(b)); return r;
}

__device__ double g_ssim_sum;   // zero-initialized at load; finalize restores 0

__global__ void finalize_kernel(float* out, double invN) {
    out[0] = (float)(1.0 - g_ssim_sum * invN);
    g_ssim_sum = 0.0;           // restore invariant for next replay
}

// Vertical blur, ONE 4-row chunk per call: 14 input rows -> 4 output rows.
// Only 20 accumulator regs live -> deep LDG pipelining (high MLP).
template<bool INTERIOR>
__device__ __forceinline__ void v_chunk(
    const float* __restrict__ p, const float* __restrict__ t,
    float* __restrict__ sV, int ty0, int col, int chunk)
{
    const int gy0 = ty0 + chunk * 4 - RAD;

    u64   acc01[4], acc23[4];
    float acc4[4];
    #pragma unroll
    for (int o = 0; o < 4; o++) { acc01[o] = 0ull; acc23[o] = 0ull; acc4[o] = 0.0f; }

    const float* pp = p + (long)gy0 * IMG_W + col;
    const float* tt = t + (long)gy0 * IMG_W + col;

    #pragma unroll
    for (int i = 0; i < 14; i++) {
        float pv, tv;
        if (INTERIOR) {
            pv = pp[i * IMG_W];
            tv = tt[i * IMG_W];
        } else {
            const bool ok = ((unsigned)(gy0 + i) < (unsigned)IMG_H);
            pv = ok ? pp[i * IMG_W] : 0.0f;
            tv = ok ? tt[i * IMG_W] : 0.0f;
        }
        const u64   a01 = pack2(pv, tv);
        const u64   a23 = mul2(a01, a01);        // (p*p, t*t)
        const float a4  = pv * tv;
        #pragma unroll
        for (int o = 0; o < 4; o++) {
            const int k = i - o;
            if (k >= 0 && k < KS) {              // compile-time pruned
                const int kk = (k < 6) ? k : (10 - k);
                const u64 ww = pack2(WK[kk], WK[kk]);
                fma2(acc01[o], a01, ww);
                fma2(acc23[o], a23, ww);
                acc4[o] = fmaf(a4, WK[kk], acc4[o]);
            }
        }
    }

    float* base = sV + col + RAD;
    #pragma unroll
    for (int o = 0; o < 4; o++) {
        const int r = chunk * 4 + o;
        float x0, x1, x2, x3;
        unpack2(acc01[o], x0, x1);
        unpack2(acc23[o], x2, x3);
        base[(0 * H_T + r) * SSTRIDE] = x0;
        base[(1 * H_T + r) * SSTRIDE] = x1;
        base[(2 * H_T + r) * SSTRIDE] = x2;
        base[(3 * H_T + r) * SSTRIDE] = x3;
        base[(4 * H_T + r) * SSTRIDE] = acc4[o];
    }
}

__global__ __launch_bounds__(NTHREADS, 2) void ssim_tile_kernel(
    const float* __restrict__ pred,
    const float* __restrict__ target)
{
    extern __shared__ float sV[];            // [5][H_T][SSTRIDE]
    __shared__ float red[NTHREADS / 32];

    const int ty0 = blockIdx.x * H_T;
    const size_t img_off = (size_t)blockIdx.y * (IMG_H * IMG_W);
    const float* __restrict__ p = pred + img_off;
    const float* __restrict__ t = target + img_off;

    // ---- zero the 10 halo columns: 5 fields * 8 rows * 10 cols = 400 ----
    if (threadIdx.x < 400) {
        const int z = threadIdx.x;
        const int cz = z % 10;
        const int rz = (z / 10) % H_T;
        const int fz = z / (10 * H_T);
        const int j = (cz < 5) ? cz : (SSTRIDE - 10 + cz);
        sV[(fz * H_T + rz) * SSTRIDE + j] = 0.0f;
    }

    // ---- Phase V: 2 chunk-tasks per thread (1024 tasks) ----
    const bool interior = (blockIdx.x > 0) && (blockIdx.x < gridDim.x - 1);
    {
        const int col0   = threadIdx.x;               // wave 0: task = tid
        const int col1   = threadIdx.x;               // wave 1: task = tid + 512
        if (interior) {
            v_chunk<true >(p, t, sV, ty0, col0, 0);
            v_chunk<true >(p, t, sV, ty0, col1, 1);
        } else {
            v_chunk<false>(p, t, sV, ty0, col0, 0);
            v_chunk<false>(p, t, sV, ty0, col1, 1);
        }
    }
    __syncthreads();

    // ---- Phase H: packed horizontal blur + SSIM (one task/thread) ----
    float ssum = 0.0f;
    {
        const int tid = threadIdx.x;
        const int r  = tid & 7;
        const int b3 = (tid >> 3) & 1;
        const int b4 = (tid >> 4) & 1;
        const int chunk = (tid >> 5) * 4 + 2 * b3 + b4;   // conflict-free remap
        const int c0 = chunk * 8;

        const float* hb = sV + r * SSTRIDE + c0;

        u64   m01[8], m23[8];
        float m4[8];
        #pragma unroll
        for (int o = 0; o < 8; o++) { m01[o] = 0ull; m23[o] = 0ull; m4[o] = 0.0f; }

        #pragma unroll
        for (int i2 = 0; i2 < 9; i2++) {
            const float2 v0 = *(const float2*)(hb + 0 * H_T * SSTRIDE + 2 * i2);
            const float2 v1 = *(const float2*)(hb + 1 * H_T * SSTRIDE + 2 * i2);
            const float2 v2 = *(const float2*)(hb + 2 * H_T * SSTRIDE + 2 * i2);
            const float2 v3 = *(const float2*)(hb + 3 * H_T * SSTRIDE + 2 * i2);
            const float2 v4 = *(const float2*)(hb + 4 * H_T * SSTRIDE + 2 * i2);
            #pragma unroll
            for (int half = 0; half < 2; half++) {
                const int i = 2 * i2 + half;
                const float a0 = half ? v0.y : v0.x;
                const float a1 = half ? v1.y : v1.x;
                const float a2 = half ? v2.y : v2.x;
                const float a3 = half ? v3.y : v3.x;
                const float a4 = half ? v4.y : v4.x;
                const u64 a01 = pack2(a0, a1);
                const u64 a23 = pack2(a2, a3);
                #pragma unroll
                for (int o = 0; o < 8; o++) {
                    const int k = i - o;
                    if (k >= 0 && k < KS) {
                        const int kk = (k < 6) ? k : (10 - k);
                        const u64 ww = pack2(WK[kk], WK[kk]);
                        fma2(m01[o], a01, ww);
                        fma2(m23[o], a23, ww);
                        m4[o] = fmaf(a4, WK[kk], m4[o]);
                    }
                }
            }
        }

        #pragma unroll
        for (int o = 0; o < 8; o++) {
            float mu_p, mu_t, bp2, bt2;
            unpack2(m01[o], mu_p, mu_t);
            unpack2(m23[o], bp2, bt2);
            const float mu_p2 = mu_p * mu_p;
            const float mu_t2 = mu_t * mu_t;
            const float mu_pt = mu_p * mu_t;
            const float sig_p  = bp2 - mu_p2;
            const float sig_t  = bt2 - mu_t2;
            const float sig_pt = m4[o] - mu_pt;
            const float num = (2.0f * mu_pt + C1F) * (2.0f * sig_pt + C2F);
            const float den = (mu_p2 + mu_t2 + C1F) * (sig_p + sig_t + C2F);
            ssum += __fdividef(num, den);
        }
    }

    // ---- block reduction -> one double atomicAdd ----
    #pragma unroll
    for (int o = 16; o > 0; o >>= 1)
        ssum += __shfl_down_sync(0xFFFFFFFFu, ssum, o);
    if ((threadIdx.x & 31) == 0)
        red[threadIdx.x >> 5] = ssum;
    __syncthreads();
    if (threadIdx.x < NTHREADS / 32) {
        float v = red[threadIdx.x];
        #pragma unroll
        for (int o = (NTHREADS / 64); o > 0; o >>= 1)
            v += __shfl_down_sync(0xFFFFFFFFu, v, o);
        if (threadIdx.x == 0)
            atomicAdd(&g_ssim_sum, (double)v);
    }
}

extern "C" void kernel_launch(void* const* d_in, const int* in_sizes, int n_in,
                              void* d_out, int out_size)
{
    const float* pred   = (const float*)d_in[0];
    const float* target = (const float*)d_in[1];
    float* out = (float*)d_out;

    const long long n = in_sizes[0];                 // 32*3*512*512
    const int imgs = (int)(n / (IMG_H * IMG_W));     // 96 planes

    cudaFuncSetAttribute(ssim_tile_kernel,
                         cudaFuncAttributeMaxDynamicSharedMemorySize, SMEM_BYTES);

    dim3 grid(IMG_H / H_T, imgs);                    // (64, 96)
    ssim_tile_kernel<<<grid, NTHREADS, SMEM_BYTES>>>(pred, target);

    finalize_kernel<<<1, 1>>>(out, 1.0 / (double)n);
}